// round 8
// baseline (speedup 1.0000x reference)
#include <cuda_runtime.h>
#include <cuda_fp16.h>
#include <cstdint>

// ---------------------------------------------------------------------------
// SpatialPolicyHead: B=256, S=128 (rows 3..66 + row 0), H=1024, D=256, V=1858
//   fp = sq_hidden @ Wf^T + bf          (B*64, 256)
//   tp = sq_hidden @ Wt^T + bt          (B*64, 256)
//   gp = hidden[:,0,:] @ Wg^T + bg      (B, 256)
//   out[b,v] = sum_d relu(fp[b,f(v),d]*tp[b,t(v),d] + gp[b,d] + promo[p(v),d])*Ws[d] + bs
//
// R8: GEMM gathers fp32 A directly (in-register fp16 fragment conversion),
// conv pass reduced to B only. Combine: 512 blocks x 512 threads (2 slices
// per batch) for 1.5x occupancy.
// ---------------------------------------------------------------------------

// scratch (static device globals -- allocation-free)
__device__ __half g_Bh[512 * 1024];     // Wf (0..255) ++ Wt (256..511), fp16
__device__ __half g_fph[16384 * 256];   // fp results, fp16
__device__ __half g_tph[16384 * 256];   // tp results, fp16
__device__ float  g_gp [256 * 256];     // [B][256] fp32

// ---------------------------------------------------------------------------
// B conversion: 128 blocks x 256 threads, 4 float4 each (512x1024 fp32->fp16).
// ---------------------------------------------------------------------------
__global__ void __launch_bounds__(256) convB_kernel(
    const float* __restrict__ Wf, const float* __restrict__ Wt)
{
    const int tid = threadIdx.x;
    const size_t base = (size_t)blockIdx.x * 1024;
    #pragma unroll
    for (int j = 0; j < 4; j++) {
        const size_t i = base + tid + j * 256;   // float4 index
        const int n  = (int)(i >> 8);
        const int c4 = (int)(i & 255);
        const float* src = (n < 256) ? (Wf + (size_t)n * 1024)
                                     : (Wt + (size_t)(n - 256) * 1024);
        const float4 v = ((const float4*)src)[c4];
        ((__half2*)g_Bh)[2 * i]     = __floats2half2_rn(v.x, v.y);
        ((__half2*)g_Bh)[2 * i + 1] = __floats2half2_rn(v.z, v.w);
    }
}

// ---------------------------------------------------------------------------
// fp16 tensor-core GEMM: grid (2,128): x=0 -> fp, 1 -> tp.
// 128x256x32 block tile, 8 warps (2m x 4n), warp tile 64x64,
// mma.sync.m16n8k16 f16->f32. A loaded fp32 straight from hidden (gathered),
// converted to fp16 in-register per fragment. 3-stage cp.async pipeline.
// smem/stage: A 128x36 fp32 (18432 B) + B 256x40 fp16 (20480 B).
// ---------------------------------------------------------------------------
#define KT 32
#define ASTF 36                  // fp32 per A smem row (144 B)
#define BSTH 40                  // fp16 per B smem row (80 B)
#define ABUFB (128 * ASTF * 4)   // A stage bytes = 18432
#define BBUFB (256 * BSTH * 2)   // B stage bytes = 20480
#define STGB  (ABUFB + BBUFB)    // 38912
#define STG 3
#define GEMM_SMEM (STG * STGB)   // 116736 B

__device__ __forceinline__ void mma_f16(float* c, const uint32_t* a, const uint32_t* b) {
    asm volatile(
        "mma.sync.aligned.m16n8k16.row.col.f32.f16.f16.f32 "
        "{%0,%1,%2,%3}, {%4,%5,%6,%7}, {%8,%9}, {%0,%1,%2,%3};"
        : "+f"(c[0]), "+f"(c[1]), "+f"(c[2]), "+f"(c[3])
        : "r"(a[0]), "r"(a[1]), "r"(a[2]), "r"(a[3]), "r"(b[0]), "r"(b[1]));
}

__device__ __forceinline__ uint32_t f2h2(float2 v) {
    const __half2 h = __floats2half2_rn(v.x, v.y);
    return *(const uint32_t*)&h;
}

__global__ void __launch_bounds__(256) gemm_fpt_kernel(
    const float* __restrict__ hidden,
    const float* __restrict__ bf, const float* __restrict__ bt)
{
    extern __shared__ char gsm[];
    uint32_t sbase;
    asm("{ .reg .u64 t; cvta.to.shared.u64 t, %1; cvt.u32.u64 %0, t; }"
        : "=r"(sbase) : "l"(gsm));

    const int tid  = threadIdx.x;
    const int bn   = blockIdx.x;    // 0 = fp, 1 = tp
    const int bm   = blockIdx.y;
    const int warp = tid >> 5;
    const int lane = tid & 31;
    const int warp_m = warp >> 2;
    const int warp_n = warp & 3;
    const int lr = lane >> 2;
    const int lc = lane & 3;

    // A copy (fp32): row = tid>>1 (2 threads/row), each thread 4x16B chunks
    const int a_row = tid >> 1;
    const int a_c0  = (tid & 1) * 4;          // first float4 index of this thread
    const int hrow  = (bm * 2 + (a_row >> 6)) * 128 + 3 + (a_row & 63);
    const float* gA = hidden + (size_t)hrow * 1024 + a_c0 * 4;
    const uint32_t sAoff = (uint32_t)((a_row * ASTF + a_c0 * 4) * 4);  // bytes

    const __half* gBbase = g_Bh + (size_t)bn * 256 * 1024;

    float acc[4][8][4];
    #pragma unroll
    for (int i = 0; i < 4; i++)
        #pragma unroll
        for (int j = 0; j < 8; j++)
            #pragma unroll
            for (int k = 0; k < 4; k++) acc[i][j][k] = 0.f;

    auto load_tile = [&](int t, int stg) {
        const uint32_t aB = sbase + (uint32_t)stg * STGB;
        const uint32_t bB = aB + ABUFB;
        #pragma unroll
        for (int j = 0; j < 4; j++)
            asm volatile("cp.async.ca.shared.global [%0], [%1], 16;" ::
                "r"(aB + sAoff + j * 16), "l"(gA + t * 32 + j * 4));
        #pragma unroll
        for (int j = 0; j < 4; j++) {
            const int id  = tid + 256 * j;
            const int row = id >> 2;
            const int cc  = id & 3;
            asm volatile("cp.async.ca.shared.global [%0], [%1], 16;" ::
                "r"(bB + (uint32_t)(row * (BSTH * 2) + cc * 16)),
                "l"(gBbase + (size_t)row * 1024 + t * 32 + cc * 8));
        }
        asm volatile("cp.async.commit_group;" ::: "memory");
    };

    // prologue: tiles 0,1 -> stages 0,1
    load_tile(0, 0);
    load_tile(1, 1);

    for (int t = 0; t < KT; t++) {
        const int stg = t % STG;
        if (t + 1 < KT) asm volatile("cp.async.wait_group 1;" ::: "memory");
        else            asm volatile("cp.async.wait_group 0;" ::: "memory");
        __syncthreads();

        if (t + 2 < KT)
            load_tile(t + 2, (t + 2) % STG);

        const float*  Ab = (const float*)(gsm + (size_t)stg * STGB);
        const __half* Bb = (const __half*)(gsm + (size_t)stg * STGB + ABUFB);
        #pragma unroll
        for (int ks = 0; ks < 2; ks++) {
            uint32_t afr[4][4], bfr[8][2];
            #pragma unroll
            for (int mt = 0; mt < 4; mt++) {
                const float* p = Ab + (warp_m * 64 + mt * 16 + lr) * ASTF + ks * 16 + 2 * lc;
                afr[mt][0] = f2h2(*(const float2*)(p));
                afr[mt][1] = f2h2(*(const float2*)(p + 8 * ASTF));
                afr[mt][2] = f2h2(*(const float2*)(p + 8));
                afr[mt][3] = f2h2(*(const float2*)(p + 8 * ASTF + 8));
            }
            #pragma unroll
            for (int nt = 0; nt < 8; nt++) {
                const __half* q = Bb + (warp_n * 64 + nt * 8 + lr) * BSTH + ks * 16 + 2 * lc;
                bfr[nt][0] = *(const uint32_t*)(q);
                bfr[nt][1] = *(const uint32_t*)(q + 8);
            }
            #pragma unroll
            for (int mt = 0; mt < 4; mt++)
                #pragma unroll
                for (int nt = 0; nt < 8; nt++)
                    mma_f16(acc[mt][nt], afr[mt], bfr[nt]);
        }
    }

    // epilogue: bias add in fp32, store fp16 half2
    const float* bia_base = bn ? bt : bf;
    __half* outp = bn ? g_tph : g_fph;
    #pragma unroll
    for (int mt = 0; mt < 4; mt++) {
        const int gm0 = bm * 128 + warp_m * 64 + mt * 16 + lr;
        #pragma unroll
        for (int nt = 0; nt < 8; nt++) {
            const int n_loc = warp_n * 64 + nt * 8 + (lc << 1);   // 0..255
            const float b0 = bia_base[n_loc], b1 = bia_base[n_loc + 1];
            *(__half2*)&outp[(size_t)gm0 * 256 + n_loc] =
                __floats2half2_rn(acc[mt][nt][0] + b0, acc[mt][nt][1] + b1);
            *(__half2*)&outp[(size_t)(gm0 + 8) * 256 + n_loc] =
                __floats2half2_rn(acc[mt][nt][2] + b0, acc[mt][nt][3] + b1);
        }
    }
}

// ---------------------------------------------------------------------------
// gp GEMM (fp32, tiny): 64 blocks x 4 batches.
// ---------------------------------------------------------------------------
__global__ void __launch_bounds__(256) gp_kernel(
    const float* __restrict__ hidden,
    const float* __restrict__ Wg, const float* __restrict__ bg)
{
    __shared__ float sh[4][1024];
    const int tid = threadIdx.x;
    const int b0  = blockIdx.x * 4;

    #pragma unroll
    for (int i = 0; i < 4; i++) {
        const int idx = tid + i * 256;
        const int row = idx >> 8;
        const int col = idx & 255;
        ((float4*)&sh[row][0])[col] =
            ((const float4*)(hidden + (size_t)(b0 + row) * 131072))[col];
    }
    __syncthreads();

    const int n = tid;
    const float4* w4 = (const float4*)(Wg + (size_t)n * 1024);
    float acc0 = 0.f, acc1 = 0.f, acc2 = 0.f, acc3 = 0.f;
    #pragma unroll 4
    for (int k4 = 0; k4 < 256; k4++) {
        const float4 w  = w4[k4];
        const float4 h0 = ((const float4*)&sh[0][0])[k4];
        const float4 h1 = ((const float4*)&sh[1][0])[k4];
        const float4 h2 = ((const float4*)&sh[2][0])[k4];
        const float4 h3 = ((const float4*)&sh[3][0])[k4];
        acc0 = fmaf(w.x, h0.x, acc0); acc0 = fmaf(w.y, h0.y, acc0);
        acc0 = fmaf(w.z, h0.z, acc0); acc0 = fmaf(w.w, h0.w, acc0);
        acc1 = fmaf(w.x, h1.x, acc1); acc1 = fmaf(w.y, h1.y, acc1);
        acc1 = fmaf(w.z, h1.z, acc1); acc1 = fmaf(w.w, h1.w, acc1);
        acc2 = fmaf(w.x, h2.x, acc2); acc2 = fmaf(w.y, h2.y, acc2);
        acc2 = fmaf(w.z, h2.z, acc2); acc2 = fmaf(w.w, h2.w, acc2);
        acc3 = fmaf(w.x, h3.x, acc3); acc3 = fmaf(w.y, h3.y, acc3);
        acc3 = fmaf(w.z, h3.z, acc3); acc3 = fmaf(w.w, h3.w, acc3);
    }
    const float bias = bg[n];
    g_gp[(size_t)(b0 + 0) * 256 + n] = acc0 + bias;
    g_gp[(size_t)(b0 + 1) * 256 + n] = acc1 + bias;
    g_gp[(size_t)(b0 + 2) * 256 + n] = acc2 + bias;
    g_gp[(size_t)(b0 + 3) * 256 + n] = acc3 + bias;
}

// ---------------------------------------------------------------------------
// Combine: 512 blocks = 2 v-slices x 256 batches, 512 threads (16 warps).
// Slices [0,930) and [930,1858) -- both even so 2-v unroll is guard-free.
// smem (fp16): fp 64x256 + tp 64x256 + gpp 5x256 = 68096 B.
// ---------------------------------------------------------------------------
__global__ void __launch_bounds__(512) combine_kernel(
    const float* __restrict__ promo_tab, const float* __restrict__ Ws,
    const float* __restrict__ bs,
    const int* __restrict__ from_sqs, const int* __restrict__ to_sqs,
    const int* __restrict__ promo_types,
    float* __restrict__ out)
{
    extern __shared__ __half hsm[];
    __half* fp_s  = hsm;            // 16384 halves
    __half* tp_s  = hsm + 16384;    // 16384 halves
    __half* gpp_s = hsm + 32768;    // 1280 halves

    const int tid   = threadIdx.x;
    const int b     = blockIdx.x >> 1;
    const int slice = blockIdx.x & 1;

    // stage fp/tp (2048 uint4 each / 512 threads = 4 each)
    {
        const uint4* sf = (const uint4*)(g_fph + (size_t)b * 16384);
        const uint4* st = (const uint4*)(g_tph + (size_t)b * 16384);
        uint4* df = (uint4*)fp_s;
        uint4* dt = (uint4*)tp_s;
        #pragma unroll
        for (int i = 0; i < 4; i++) {
            df[tid + i * 512] = sf[tid + i * 512];
            dt[tid + i * 512] = st[tid + i * 512];
        }
        // gpp: 640 half2; p = i>>7, d2 = i&127
        for (int i = tid; i < 640; i += 512) {
            const int p  = i >> 7;
            const int d2 = i & 127;
            const float2 pv = ((const float2*)(promo_tab + p * 256))[d2];
            const float2 gv = ((const float2*)(g_gp + (size_t)b * 256))[d2];
            ((__half2*)gpp_s)[i] = __floats2half2_rn(pv.x + gv.x, pv.y + gv.y);
        }
    }

    const int lane = tid & 31;
    const int warp = tid >> 5;

    // register-hoisted Ws for d = lane*8 .. lane*8+7
    const float4 wsa = *(const float4*)(Ws + lane * 8);
    const float4 wsb = *(const float4*)(Ws + lane * 8 + 4);
    const float wsr[8] = { wsa.x, wsa.y, wsa.z, wsa.w, wsb.x, wsb.y, wsb.z, wsb.w };
    const float bs0 = __ldg(bs);
    const __half2 hzero = __float2half2_rn(0.f);

    __syncthreads();

    const int vstart = slice ? 930 : 0;
    const int vend   = slice ? 1858 : 930;

    for (int v0 = vstart + warp * 2; v0 < vend; v0 += 32) {
        const int v1 = v0 + 1;
        const int f0 = __ldg(from_sqs + v0),    f1 = __ldg(from_sqs + v1);
        const int t0 = __ldg(to_sqs + v0),      t1 = __ldg(to_sqs + v1);
        const int p0 = __ldg(promo_types + v0), p1 = __ldg(promo_types + v1);

        const uint4 fh0 = *(const uint4*)(fp_s  + f0 * 256 + lane * 8);
        const uint4 th0 = *(const uint4*)(tp_s  + t0 * 256 + lane * 8);
        const uint4 gh0 = *(const uint4*)(gpp_s + p0 * 256 + lane * 8);
        const uint4 fh1 = *(const uint4*)(fp_s  + f1 * 256 + lane * 8);
        const uint4 th1 = *(const uint4*)(tp_s  + t1 * 256 + lane * 8);
        const uint4 gh1 = *(const uint4*)(gpp_s + p1 * 256 + lane * 8);

        const uint32_t* fw0 = (const uint32_t*)&fh0;
        const uint32_t* tw0 = (const uint32_t*)&th0;
        const uint32_t* gw0 = (const uint32_t*)&gh0;
        const uint32_t* fw1 = (const uint32_t*)&fh1;
        const uint32_t* tw1 = (const uint32_t*)&th1;
        const uint32_t* gw1 = (const uint32_t*)&gh1;

        float acc0 = 0.f, acc1 = 0.f;
        #pragma unroll
        for (int j = 0; j < 4; j++) {
            __half2 c0 = __hfma2(*(const __half2*)&fw0[j], *(const __half2*)&tw0[j],
                                 *(const __half2*)&gw0[j]);
            __half2 c1 = __hfma2(*(const __half2*)&fw1[j], *(const __half2*)&tw1[j],
                                 *(const __half2*)&gw1[j]);
            c0 = __hmax2(c0, hzero);
            c1 = __hmax2(c1, hzero);
            const float2 r0 = __half22float2(c0);
            const float2 r1 = __half22float2(c1);
            acc0 = fmaf(r0.x, wsr[2*j],     acc0);
            acc0 = fmaf(r0.y, wsr[2*j + 1], acc0);
            acc1 = fmaf(r1.x, wsr[2*j],     acc1);
            acc1 = fmaf(r1.y, wsr[2*j + 1], acc1);
        }

        #pragma unroll
        for (int off = 16; off > 0; off >>= 1) {
            acc0 += __shfl_xor_sync(0xffffffffu, acc0, off);
            acc1 += __shfl_xor_sync(0xffffffffu, acc1, off);
        }
        if (lane == 0) {
            out[(size_t)b * 1858 + v0] = acc0 + bs0;
            out[(size_t)b * 1858 + v1] = acc1 + bs0;
        }
    }
}

// ---------------------------------------------------------------------------
extern "C" void kernel_launch(void* const* d_in, const int* in_sizes, int n_in,
                              void* d_out, int out_size)
{
    (void)in_sizes; (void)n_in; (void)out_size;

    const float* hidden      = (const float*)d_in[0];
    const float* Wf          = (const float*)d_in[1];
    const float* bf          = (const float*)d_in[2];
    const float* Wt          = (const float*)d_in[3];
    const float* bt          = (const float*)d_in[4];
    const float* Wg          = (const float*)d_in[5];
    const float* bg          = (const float*)d_in[6];
    const float* promo_tab   = (const float*)d_in[7];
    const float* Ws          = (const float*)d_in[8];
    const float* bs          = (const float*)d_in[9];
    const int*   from_sqs    = (const int*)d_in[10];
    const int*   to_sqs      = (const int*)d_in[11];
    const int*   promo_types = (const int*)d_in[12];
    float*       out         = (float*)d_out;

    // 1) B fp16 conversion (tiny)
    convB_kernel<<<128, 256>>>(Wf, Wt);

    // 2) fp16 tensor-core fp/tp GEMM (fp32-A gather, 3-stage pipeline)
    cudaFuncSetAttribute(gemm_fpt_kernel,
                         cudaFuncAttributeMaxDynamicSharedMemorySize, GEMM_SMEM);
    gemm_fpt_kernel<<<dim3(2, 128), 256, GEMM_SMEM>>>(hidden, bf, bt);

    // 3) gp
    gp_kernel<<<64, 256>>>(hidden, Wg, bg);

    // 4) combine: 2 v-slices x 256 batches
    const int comb_smem = (16384 + 16384 + 1280) * 2;   // 68096 B
    cudaFuncSetAttribute(combine_kernel,
                         cudaFuncAttributeMaxDynamicSharedMemorySize, comb_smem);
    combine_kernel<<<512, 512, comb_smem>>>(promo_tab, Ws, bs,
                                            from_sqs, to_sqs, promo_types, out);
}

// round 9
// speedup vs baseline: 1.0514x; 1.0514x over previous
#include <cuda_runtime.h>
#include <cuda_fp16.h>
#include <cstdint>

// ---------------------------------------------------------------------------
// SpatialPolicyHead: B=256, S=128 (rows 3..66 + row 0), H=1024, D=256, V=1858
//   fp = sq_hidden @ Wf^T + bf          (B*64, 256)
//   tp = sq_hidden @ Wt^T + bt          (B*64, 256)
//   gp = hidden[:,0,:] @ Wg^T + bg      (B, 256)
//   out[b,v] = sum_d relu(fp[b,f(v),d]*tp[b,t(v),d] + gp[b,d] + promo[p(v),d])*Ws[d] + bs
//
// R9: revert to R7 everywhere except GEMM: 128x128 block tile (warp 64x32),
// 2-stage pipeline, 2 CTAs/SM (__launch_bounds__(256,2)) for latency hiding.
// ---------------------------------------------------------------------------

// scratch (static device globals -- allocation-free)
__device__ __half g_Ah[16384 * 1024];   // gathered sq_hidden rows, fp16
__device__ __half g_Bh[512 * 1024];     // Wf (0..255) ++ Wt (256..511), fp16
__device__ __half g_fph[16384 * 256];   // fp results, fp16
__device__ __half g_tph[16384 * 256];   // tp results, fp16
__device__ float  g_gp [256 * 256];     // [B][256] fp32

// ---------------------------------------------------------------------------
// Pre-pass: gather + fp16-convert A; convert B.
// ---------------------------------------------------------------------------
__global__ void __launch_bounds__(256) conv_kernel(
    const float* __restrict__ hidden,
    const float* __restrict__ Wf, const float* __restrict__ Wt)
{
    const int tid = threadIdx.x;
    if (blockIdx.x < 4096) {
        const size_t base = (size_t)blockIdx.x * 1024;
        #pragma unroll
        for (int j = 0; j < 4; j++) {
            const size_t i = base + tid + j * 256;   // float4 index
            const int m  = (int)(i >> 8);
            const int c4 = (int)(i & 255);
            const int row = (m >> 6) * 128 + 3 + (m & 63);
            const float4 v = ((const float4*)(hidden + (size_t)row * 1024))[c4];
            ((__half2*)g_Ah)[2 * i]     = __floats2half2_rn(v.x, v.y);
            ((__half2*)g_Ah)[2 * i + 1] = __floats2half2_rn(v.z, v.w);
        }
    } else {
        const size_t base = (size_t)(blockIdx.x - 4096) * 1024;
        #pragma unroll
        for (int j = 0; j < 4; j++) {
            const size_t i = base + tid + j * 256;
            const int n  = (int)(i >> 8);
            const int c4 = (int)(i & 255);
            const float* src = (n < 256) ? (Wf + (size_t)n * 1024)
                                         : (Wt + (size_t)(n - 256) * 1024);
            const float4 v = ((const float4*)src)[c4];
            ((__half2*)g_Bh)[2 * i]     = __floats2half2_rn(v.x, v.y);
            ((__half2*)g_Bh)[2 * i + 1] = __floats2half2_rn(v.z, v.w);
        }
    }
}

// ---------------------------------------------------------------------------
// fp16 tensor-core GEMM: grid (4,128). Block tile 128(m) x 128(n) x 32(k),
// 8 warps (2m x 4n), warp tile 64x32, mma.sync.m16n8k16 f16->f32,
// 2-stage cp.async pipeline, 2 CTAs/SM.
// n_glob = bn*128 + local: 0..255 -> fp (Wf/bf), 256..511 -> tp (Wt/bt).
// smem/stage: A 128x40h + B 128x40h = 20480 B; total 40960 B.
// ---------------------------------------------------------------------------
#define KT 32
#define AST 40                   // halves per smem row (80 B)
#define TBUFH (128 * AST)        // halves per (A or B) buffer
#define GEMM_SMEM (4 * TBUFH * 2)   // 40960 B

__device__ __forceinline__ void mma_f16(float* c, const uint32_t* a, const uint32_t* b) {
    asm volatile(
        "mma.sync.aligned.m16n8k16.row.col.f32.f16.f16.f32 "
        "{%0,%1,%2,%3}, {%4,%5,%6,%7}, {%8,%9}, {%0,%1,%2,%3};"
        : "+f"(c[0]), "+f"(c[1]), "+f"(c[2]), "+f"(c[3])
        : "r"(a[0]), "r"(a[1]), "r"(a[2]), "r"(a[3]), "r"(b[0]), "r"(b[1]));
}

__global__ void __launch_bounds__(256, 2) gemm_fpt_kernel(
    const float* __restrict__ bf, const float* __restrict__ bt)
{
    extern __shared__ __half hsm[];
    // layout: [2 stages][A 128x40 | B 128x40]
    uint32_t sbase;
    asm("{ .reg .u64 t; cvta.to.shared.u64 t, %1; cvt.u32.u64 %0, t; }"
        : "=r"(sbase) : "l"(hsm));

    const int tid  = threadIdx.x;
    const int bn   = blockIdx.x;    // 0..3
    const int bm   = blockIdx.y;    // 0..127
    const int warp = tid >> 5;
    const int lane = tid & 31;
    const int warp_m = warp >> 2;   // 0..1
    const int warp_n = warp & 3;    // 0..3
    const int lr = lane >> 2;       // 0..7
    const int lc = lane & 3;        // 0..3

    // copies: row = tid>>1, 2x16B chunks at cc = (tid&1)*2
    const int c_row = tid >> 1;
    const int c_cc  = (tid & 1) * 2;
    const __half* gA = g_Ah + (size_t)(bm * 128 + c_row) * 1024 + c_cc * 8;
    const __half* gB = g_Bh + (size_t)(bn * 128 + c_row) * 1024 + c_cc * 8;
    const uint32_t sOff = (uint32_t)(c_row * (AST * 2) + c_cc * 16);

    float acc[4][4][4];
    #pragma unroll
    for (int i = 0; i < 4; i++)
        #pragma unroll
        for (int j = 0; j < 4; j++)
            #pragma unroll
            for (int k = 0; k < 4; k++) acc[i][j][k] = 0.f;

    auto load_tile = [&](int t, int stg) {
        const uint32_t aB = sbase + (uint32_t)stg * (2 * TBUFH * 2);
        const uint32_t bB = aB + TBUFH * 2;
        asm volatile("cp.async.ca.shared.global [%0], [%1], 16;" ::
            "r"(aB + sOff), "l"(gA + t * 32));
        asm volatile("cp.async.ca.shared.global [%0], [%1], 16;" ::
            "r"(aB + sOff + 16), "l"(gA + t * 32 + 8));
        asm volatile("cp.async.ca.shared.global [%0], [%1], 16;" ::
            "r"(bB + sOff), "l"(gB + t * 32));
        asm volatile("cp.async.ca.shared.global [%0], [%1], 16;" ::
            "r"(bB + sOff + 16), "l"(gB + t * 32 + 8));
        asm volatile("cp.async.commit_group;" ::: "memory");
    };

    load_tile(0, 0);

    int stg = 0;
    for (int t = 0; t < KT; t++) {
        asm volatile("cp.async.wait_group 0;" ::: "memory");
        __syncthreads();

        if (t + 1 < KT)
            load_tile(t + 1, stg ^ 1);

        const __half* Ab = hsm + (size_t)stg * (2 * TBUFH);
        const __half* Bb = Ab + TBUFH;
        #pragma unroll
        for (int ks = 0; ks < 2; ks++) {
            uint32_t afr[4][4], bfr[4][2];
            #pragma unroll
            for (int mt = 0; mt < 4; mt++) {
                const __half* p = Ab + (warp_m * 64 + mt * 16 + lr) * AST + ks * 16 + 2 * lc;
                afr[mt][0] = *(const uint32_t*)(p);
                afr[mt][1] = *(const uint32_t*)(p + 8 * AST);
                afr[mt][2] = *(const uint32_t*)(p + 8);
                afr[mt][3] = *(const uint32_t*)(p + 8 * AST + 8);
            }
            #pragma unroll
            for (int nt = 0; nt < 4; nt++) {
                const __half* q = Bb + (warp_n * 32 + nt * 8 + lr) * AST + ks * 16 + 2 * lc;
                bfr[nt][0] = *(const uint32_t*)(q);
                bfr[nt][1] = *(const uint32_t*)(q + 8);
            }
            #pragma unroll
            for (int mt = 0; mt < 4; mt++)
                #pragma unroll
                for (int nt = 0; nt < 4; nt++)
                    mma_f16(acc[mt][nt], afr[mt], bfr[nt]);
        }
        stg ^= 1;
    }

    // epilogue: bias add in fp32, store fp16 half2.
    // n_glob = bn*128 + warp_n*32 + nt*8 + 2*lc; bn<2 -> fp, else tp.
    const bool is_tp = (bn >= 2);
    const float* bia_base = is_tp ? bt : bf;
    __half* outp = is_tp ? g_tph : g_fph;
    const int ncol0 = (bn & 1) * 128;
    #pragma unroll
    for (int mt = 0; mt < 4; mt++) {
        const int gm0 = bm * 128 + warp_m * 64 + mt * 16 + lr;
        #pragma unroll
        for (int nt = 0; nt < 4; nt++) {
            const int n_loc = ncol0 + warp_n * 32 + nt * 8 + (lc << 1);   // 0..255
            const float b0 = bia_base[n_loc], b1 = bia_base[n_loc + 1];
            *(__half2*)&outp[(size_t)gm0 * 256 + n_loc] =
                __floats2half2_rn(acc[mt][nt][0] + b0, acc[mt][nt][1] + b1);
            *(__half2*)&outp[(size_t)(gm0 + 8) * 256 + n_loc] =
                __floats2half2_rn(acc[mt][nt][2] + b0, acc[mt][nt][3] + b1);
        }
    }
}

// ---------------------------------------------------------------------------
// gp GEMM (fp32, tiny): 64 blocks x 4 batches.
// ---------------------------------------------------------------------------
__global__ void __launch_bounds__(256) gp_kernel(
    const float* __restrict__ hidden,
    const float* __restrict__ Wg, const float* __restrict__ bg)
{
    __shared__ float sh[4][1024];
    const int tid = threadIdx.x;
    const int b0  = blockIdx.x * 4;

    #pragma unroll
    for (int i = 0; i < 4; i++) {
        const int idx = tid + i * 256;
        const int row = idx >> 8;
        const int col = idx & 255;
        ((float4*)&sh[row][0])[col] =
            ((const float4*)(hidden + (size_t)(b0 + row) * 131072))[col];
    }
    __syncthreads();

    const int n = tid;
    const float4* w4 = (const float4*)(Wg + (size_t)n * 1024);
    float acc0 = 0.f, acc1 = 0.f, acc2 = 0.f, acc3 = 0.f;
    #pragma unroll 4
    for (int k4 = 0; k4 < 256; k4++) {
        const float4 w  = w4[k4];
        const float4 h0 = ((const float4*)&sh[0][0])[k4];
        const float4 h1 = ((const float4*)&sh[1][0])[k4];
        const float4 h2 = ((const float4*)&sh[2][0])[k4];
        const float4 h3 = ((const float4*)&sh[3][0])[k4];
        acc0 = fmaf(w.x, h0.x, acc0); acc0 = fmaf(w.y, h0.y, acc0);
        acc0 = fmaf(w.z, h0.z, acc0); acc0 = fmaf(w.w, h0.w, acc0);
        acc1 = fmaf(w.x, h1.x, acc1); acc1 = fmaf(w.y, h1.y, acc1);
        acc1 = fmaf(w.z, h1.z, acc1); acc1 = fmaf(w.w, h1.w, acc1);
        acc2 = fmaf(w.x, h2.x, acc2); acc2 = fmaf(w.y, h2.y, acc2);
        acc2 = fmaf(w.z, h2.z, acc2); acc2 = fmaf(w.w, h2.w, acc2);
        acc3 = fmaf(w.x, h3.x, acc3); acc3 = fmaf(w.y, h3.y, acc3);
        acc3 = fmaf(w.z, h3.z, acc3); acc3 = fmaf(w.w, h3.w, acc3);
    }
    const float bias = bg[n];
    g_gp[(size_t)(b0 + 0) * 256 + n] = acc0 + bias;
    g_gp[(size_t)(b0 + 1) * 256 + n] = acc1 + bias;
    g_gp[(size_t)(b0 + 2) * 256 + n] = acc2 + bias;
    g_gp[(size_t)(b0 + 3) * 256 + n] = acc3 + bias;
}

// ---------------------------------------------------------------------------
// Combine (R7 config): 256 blocks (one per batch), 1024 threads (32 warps).
// smem (fp16): fp 64x256 + tp 64x256 + gpp 5x256 = 68096 B, where
// gpp[p][d] = gp[b][d] + promo[p][d]. 2 v per warp iteration.
// ---------------------------------------------------------------------------
__global__ void __launch_bounds__(1024) combine_kernel(
    const float* __restrict__ promo_tab, const float* __restrict__ Ws,
    const float* __restrict__ bs,
    const int* __restrict__ from_sqs, const int* __restrict__ to_sqs,
    const int* __restrict__ promo_types,
    float* __restrict__ out)
{
    extern __shared__ __half hsm2[];
    __half* fp_s  = hsm2;            // 16384 halves
    __half* tp_s  = hsm2 + 16384;    // 16384 halves
    __half* gpp_s = hsm2 + 32768;    // 1280 halves

    const int tid = threadIdx.x;
    const int b   = blockIdx.x;

    {
        const uint4* sf = (const uint4*)(g_fph + (size_t)b * 16384);
        const uint4* st = (const uint4*)(g_tph + (size_t)b * 16384);
        uint4* df = (uint4*)fp_s;
        uint4* dt = (uint4*)tp_s;
        df[tid] = sf[tid]; df[tid + 1024] = sf[tid + 1024];
        dt[tid] = st[tid]; dt[tid + 1024] = st[tid + 1024];
        if (tid < 640) {
            const int p  = tid >> 7;
            const int d2 = tid & 127;
            const float2 pv = ((const float2*)(promo_tab + p * 256))[d2];
            const float2 gv = ((const float2*)(g_gp + (size_t)b * 256))[d2];
            ((__half2*)gpp_s)[tid] = __floats2half2_rn(pv.x + gv.x, pv.y + gv.y);
        }
    }

    const int lane = tid & 31;
    const int warp = tid >> 5;

    const float4 wsa = *(const float4*)(Ws + lane * 8);
    const float4 wsb = *(const float4*)(Ws + lane * 8 + 4);
    const float wsr[8] = { wsa.x, wsa.y, wsa.z, wsa.w, wsb.x, wsb.y, wsb.z, wsb.w };
    const float bs0 = __ldg(bs);
    const __half2 hzero = __float2half2_rn(0.f);

    __syncthreads();

    for (int v0 = warp * 2; v0 < 1858; v0 += 64) {
        const int v1 = v0 + 1;
        const int f0 = __ldg(from_sqs + v0),    f1 = __ldg(from_sqs + v1);
        const int t0 = __ldg(to_sqs + v0),      t1 = __ldg(to_sqs + v1);
        const int p0 = __ldg(promo_types + v0), p1 = __ldg(promo_types + v1);

        const uint4 fh0 = *(const uint4*)(fp_s  + f0 * 256 + lane * 8);
        const uint4 th0 = *(const uint4*)(tp_s  + t0 * 256 + lane * 8);
        const uint4 gh0 = *(const uint4*)(gpp_s + p0 * 256 + lane * 8);
        const uint4 fh1 = *(const uint4*)(fp_s  + f1 * 256 + lane * 8);
        const uint4 th1 = *(const uint4*)(tp_s  + t1 * 256 + lane * 8);
        const uint4 gh1 = *(const uint4*)(gpp_s + p1 * 256 + lane * 8);

        const uint32_t* fw0 = (const uint32_t*)&fh0;
        const uint32_t* tw0 = (const uint32_t*)&th0;
        const uint32_t* gw0 = (const uint32_t*)&gh0;
        const uint32_t* fw1 = (const uint32_t*)&fh1;
        const uint32_t* tw1 = (const uint32_t*)&th1;
        const uint32_t* gw1 = (const uint32_t*)&gh1;

        float acc0 = 0.f, acc1 = 0.f;
        #pragma unroll
        for (int j = 0; j < 4; j++) {
            __half2 c0 = __hfma2(*(const __half2*)&fw0[j], *(const __half2*)&tw0[j],
                                 *(const __half2*)&gw0[j]);
            __half2 c1 = __hfma2(*(const __half2*)&fw1[j], *(const __half2*)&tw1[j],
                                 *(const __half2*)&gw1[j]);
            c0 = __hmax2(c0, hzero);
            c1 = __hmax2(c1, hzero);
            const float2 r0 = __half22float2(c0);
            const float2 r1 = __half22float2(c1);
            acc0 = fmaf(r0.x, wsr[2*j],     acc0);
            acc0 = fmaf(r0.y, wsr[2*j + 1], acc0);
            acc1 = fmaf(r1.x, wsr[2*j],     acc1);
            acc1 = fmaf(r1.y, wsr[2*j + 1], acc1);
        }

        #pragma unroll
        for (int off = 16; off > 0; off >>= 1) {
            acc0 += __shfl_xor_sync(0xffffffffu, acc0, off);
            acc1 += __shfl_xor_sync(0xffffffffu, acc1, off);
        }
        if (lane == 0) {
            out[(size_t)b * 1858 + v0] = acc0 + bs0;
            out[(size_t)b * 1858 + v1] = acc1 + bs0;
        }
    }
}

// ---------------------------------------------------------------------------
extern "C" void kernel_launch(void* const* d_in, const int* in_sizes, int n_in,
                              void* d_out, int out_size)
{
    (void)in_sizes; (void)n_in; (void)out_size;

    const float* hidden      = (const float*)d_in[0];
    const float* Wf          = (const float*)d_in[1];
    const float* bf          = (const float*)d_in[2];
    const float* Wt          = (const float*)d_in[3];
    const float* bt          = (const float*)d_in[4];
    const float* Wg          = (const float*)d_in[5];
    const float* bg          = (const float*)d_in[6];
    const float* promo_tab   = (const float*)d_in[7];
    const float* Ws          = (const float*)d_in[8];
    const float* bs          = (const float*)d_in[9];
    const int*   from_sqs    = (const int*)d_in[10];
    const int*   to_sqs      = (const int*)d_in[11];
    const int*   promo_types = (const int*)d_in[12];
    float*       out         = (float*)d_out;

    // 1) gather + fp16 convert pre-pass
    conv_kernel<<<4224, 256>>>(hidden, Wf, Wt);

    // 2) fp16 tensor-core fp/tp GEMM (128x128 tiles, 2 CTAs/SM)
    cudaFuncSetAttribute(gemm_fpt_kernel,
                         cudaFuncAttributeMaxDynamicSharedMemorySize, GEMM_SMEM);
    gemm_fpt_kernel<<<dim3(4, 128), 256, GEMM_SMEM>>>(bf, bt);

    // 3) gp
    gp_kernel<<<64, 256>>>(hidden, Wg, bg);

    // 4) combine (R7 config)
    const int comb_smem = (16384 + 16384 + 1280) * 2;   // 68096 B
    cudaFuncSetAttribute(combine_kernel,
                         cudaFuncAttributeMaxDynamicSharedMemorySize, comb_smem);
    combine_kernel<<<256, 1024, comb_smem>>>(promo_tab, Ws, bs,
                                             from_sqs, to_sqs, promo_types, out);
}

// round 10
// speedup vs baseline: 1.1462x; 1.0902x over previous
#include <cuda_runtime.h>
#include <cuda_fp16.h>
#include <cstdint>

// ---------------------------------------------------------------------------
// SpatialPolicyHead: B=256, S=128 (rows 3..66 + row 0), H=1024, D=256, V=1858
//   fp = sq_hidden @ Wf^T + bf          (B*64, 256)
//   tp = sq_hidden @ Wt^T + bt          (B*64, 256)
//   gp = hidden[:,0,:] @ Wg^T + bg      (B, 256)
//   out[b,v] = sum_d relu(fp[b,f(v),d]*tp[b,t(v),d] + gp[b,d] + promo[p(v),d])*Ws[d] + bs
//
// R10: GEMM 128x256 tile with 16 warps (warp tile 32x64) -> 2x warps/SM at
// same smem; combine gets a 6-shfl dual reduction. Rest identical to R7.
// ---------------------------------------------------------------------------

// scratch (static device globals -- allocation-free)
__device__ __half g_Ah[16384 * 1024];   // gathered sq_hidden rows, fp16
__device__ __half g_Bh[512 * 1024];     // Wf (0..255) ++ Wt (256..511), fp16
__device__ __half g_fph[16384 * 256];   // fp results, fp16
__device__ __half g_tph[16384 * 256];   // tp results, fp16
__device__ float  g_gp [256 * 256];     // [B][256] fp32

// ---------------------------------------------------------------------------
// Pre-pass: gather + fp16-convert A; convert B.
// ---------------------------------------------------------------------------
__global__ void __launch_bounds__(256) conv_kernel(
    const float* __restrict__ hidden,
    const float* __restrict__ Wf, const float* __restrict__ Wt)
{
    const int tid = threadIdx.x;
    if (blockIdx.x < 4096) {
        const size_t base = (size_t)blockIdx.x * 1024;
        #pragma unroll
        for (int j = 0; j < 4; j++) {
            const size_t i = base + tid + j * 256;   // float4 index
            const int m  = (int)(i >> 8);
            const int c4 = (int)(i & 255);
            const int row = (m >> 6) * 128 + 3 + (m & 63);
            const float4 v = ((const float4*)(hidden + (size_t)row * 1024))[c4];
            ((__half2*)g_Ah)[2 * i]     = __floats2half2_rn(v.x, v.y);
            ((__half2*)g_Ah)[2 * i + 1] = __floats2half2_rn(v.z, v.w);
        }
    } else {
        const size_t base = (size_t)(blockIdx.x - 4096) * 1024;
        #pragma unroll
        for (int j = 0; j < 4; j++) {
            const size_t i = base + tid + j * 256;
            const int n  = (int)(i >> 8);
            const int c4 = (int)(i & 255);
            const float* src = (n < 256) ? (Wf + (size_t)n * 1024)
                                         : (Wt + (size_t)(n - 256) * 1024);
            const float4 v = ((const float4*)src)[c4];
            ((__half2*)g_Bh)[2 * i]     = __floats2half2_rn(v.x, v.y);
            ((__half2*)g_Bh)[2 * i + 1] = __floats2half2_rn(v.z, v.w);
        }
    }
}

// ---------------------------------------------------------------------------
// fp16 tensor-core GEMM: grid (2,128): x=0 -> fp, 1 -> tp.
// 128(m) x 256(n) x 32(k) block tile, 512 threads = 16 warps (4m x 4n),
// warp tile 32x64 (acc 64 regs). mma.sync.m16n8k16 f16->f32,
// 3-stage cp.async pipeline. smem/stage: A 128x40h + B 256x40h = 30720 B.
// ---------------------------------------------------------------------------
#define KT 32
#define AST 40                   // halves per smem row (80 B)
#define ABUFH (128 * AST)
#define BBUFH (256 * AST)
#define STG 3
#define GEMM_SMEM (STG * (ABUFH + BBUFH) * 2)   // 92160 B

__device__ __forceinline__ void mma_f16(float* c, const uint32_t* a, const uint32_t* b) {
    asm volatile(
        "mma.sync.aligned.m16n8k16.row.col.f32.f16.f16.f32 "
        "{%0,%1,%2,%3}, {%4,%5,%6,%7}, {%8,%9}, {%0,%1,%2,%3};"
        : "+f"(c[0]), "+f"(c[1]), "+f"(c[2]), "+f"(c[3])
        : "r"(a[0]), "r"(a[1]), "r"(a[2]), "r"(a[3]), "r"(b[0]), "r"(b[1]));
}

__global__ void __launch_bounds__(512) gemm_fpt_kernel(
    const float* __restrict__ bf, const float* __restrict__ bt)
{
    extern __shared__ __half hsm[];
    uint32_t sbase;
    asm("{ .reg .u64 t; cvta.to.shared.u64 t, %1; cvt.u32.u64 %0, t; }"
        : "=r"(sbase) : "l"(hsm));

    const int tid  = threadIdx.x;
    const int bn   = blockIdx.x;    // 0 = fp, 1 = tp
    const int bm   = blockIdx.y;
    const int warp = tid >> 5;
    const int lane = tid & 31;
    const int warp_m = warp >> 2;   // 0..3
    const int warp_n = warp & 3;    // 0..3
    const int lr = lane >> 2;       // 0..7
    const int lc = lane & 3;        // 0..3

    // A copy: 512 chunks (128 rows x 4 x 16B) -> 1 chunk/thread
    const int a_row = tid >> 2;
    const int a_cc  = tid & 3;
    const __half* gA = g_Ah + (size_t)(bm * 128 + a_row) * 1024 + a_cc * 8;
    const uint32_t sAoff = (uint32_t)(a_row * (AST * 2) + a_cc * 16);

    // B copy: 1024 chunks (256 rows x 4 x 16B) -> 2 chunks/thread
    const __half* gBbase = g_Bh + (size_t)bn * 256 * 1024;

    float acc[2][8][4];
    #pragma unroll
    for (int i = 0; i < 2; i++)
        #pragma unroll
        for (int j = 0; j < 8; j++)
            #pragma unroll
            for (int k = 0; k < 4; k++) acc[i][j][k] = 0.f;

    auto load_tile = [&](int t, int stg) {
        const uint32_t aB = sbase + (uint32_t)stg * (ABUFH + BBUFH) * 2;
        const uint32_t bB = aB + ABUFH * 2;
        asm volatile("cp.async.ca.shared.global [%0], [%1], 16;" ::
            "r"(aB + sAoff), "l"(gA + t * 32));
        #pragma unroll
        for (int j = 0; j < 2; j++) {
            const int id  = tid + 512 * j;
            const int row = id >> 2;
            const int cc  = id & 3;
            asm volatile("cp.async.ca.shared.global [%0], [%1], 16;" ::
                "r"(bB + (uint32_t)(row * (AST * 2) + cc * 16)),
                "l"(gBbase + (size_t)row * 1024 + t * 32 + cc * 8));
        }
        asm volatile("cp.async.commit_group;" ::: "memory");
    };

    // prologue: tiles 0,1 -> stages 0,1
    load_tile(0, 0);
    load_tile(1, 1);

    for (int t = 0; t < KT; t++) {
        const int stg = t % STG;
        if (t + 1 < KT) asm volatile("cp.async.wait_group 1;" ::: "memory");
        else            asm volatile("cp.async.wait_group 0;" ::: "memory");
        __syncthreads();

        if (t + 2 < KT)
            load_tile(t + 2, (t + 2) % STG);

        const __half* Ab = hsm + (size_t)stg * (ABUFH + BBUFH);
        const __half* Bb = Ab + ABUFH;
        #pragma unroll
        for (int ks = 0; ks < 2; ks++) {
            uint32_t afr[2][4], bfr[8][2];
            #pragma unroll
            for (int mt = 0; mt < 2; mt++) {
                const __half* p = Ab + (warp_m * 32 + mt * 16 + lr) * AST + ks * 16 + 2 * lc;
                afr[mt][0] = *(const uint32_t*)(p);
                afr[mt][1] = *(const uint32_t*)(p + 8 * AST);
                afr[mt][2] = *(const uint32_t*)(p + 8);
                afr[mt][3] = *(const uint32_t*)(p + 8 * AST + 8);
            }
            #pragma unroll
            for (int nt = 0; nt < 8; nt++) {
                const __half* q = Bb + (warp_n * 64 + nt * 8 + lr) * AST + ks * 16 + 2 * lc;
                bfr[nt][0] = *(const uint32_t*)(q);
                bfr[nt][1] = *(const uint32_t*)(q + 8);
            }
            #pragma unroll
            for (int mt = 0; mt < 2; mt++)
                #pragma unroll
                for (int nt = 0; nt < 8; nt++)
                    mma_f16(acc[mt][nt], afr[mt], bfr[nt]);
        }
    }

    // epilogue: bias add in fp32, store fp16 half2
    const float* bia_base = bn ? bt : bf;
    __half* outp = bn ? g_tph : g_fph;
    #pragma unroll
    for (int mt = 0; mt < 2; mt++) {
        const int gm0 = bm * 128 + warp_m * 32 + mt * 16 + lr;
        #pragma unroll
        for (int nt = 0; nt < 8; nt++) {
            const int n_loc = warp_n * 64 + nt * 8 + (lc << 1);   // 0..255
            const float b0 = bia_base[n_loc], b1 = bia_base[n_loc + 1];
            *(__half2*)&outp[(size_t)gm0 * 256 + n_loc] =
                __floats2half2_rn(acc[mt][nt][0] + b0, acc[mt][nt][1] + b1);
            *(__half2*)&outp[(size_t)(gm0 + 8) * 256 + n_loc] =
                __floats2half2_rn(acc[mt][nt][2] + b0, acc[mt][nt][3] + b1);
        }
    }
}

// ---------------------------------------------------------------------------
// gp GEMM (fp32, tiny): 64 blocks x 4 batches.
// ---------------------------------------------------------------------------
__global__ void __launch_bounds__(256) gp_kernel(
    const float* __restrict__ hidden,
    const float* __restrict__ Wg, const float* __restrict__ bg)
{
    __shared__ float sh[4][1024];
    const int tid = threadIdx.x;
    const int b0  = blockIdx.x * 4;

    #pragma unroll
    for (int i = 0; i < 4; i++) {
        const int idx = tid + i * 256;
        const int row = idx >> 8;
        const int col = idx & 255;
        ((float4*)&sh[row][0])[col] =
            ((const float4*)(hidden + (size_t)(b0 + row) * 131072))[col];
    }
    __syncthreads();

    const int n = tid;
    const float4* w4 = (const float4*)(Wg + (size_t)n * 1024);
    float acc0 = 0.f, acc1 = 0.f, acc2 = 0.f, acc3 = 0.f;
    #pragma unroll 4
    for (int k4 = 0; k4 < 256; k4++) {
        const float4 w  = w4[k4];
        const float4 h0 = ((const float4*)&sh[0][0])[k4];
        const float4 h1 = ((const float4*)&sh[1][0])[k4];
        const float4 h2 = ((const float4*)&sh[2][0])[k4];
        const float4 h3 = ((const float4*)&sh[3][0])[k4];
        acc0 = fmaf(w.x, h0.x, acc0); acc0 = fmaf(w.y, h0.y, acc0);
        acc0 = fmaf(w.z, h0.z, acc0); acc0 = fmaf(w.w, h0.w, acc0);
        acc1 = fmaf(w.x, h1.x, acc1); acc1 = fmaf(w.y, h1.y, acc1);
        acc1 = fmaf(w.z, h1.z, acc1); acc1 = fmaf(w.w, h1.w, acc1);
        acc2 = fmaf(w.x, h2.x, acc2); acc2 = fmaf(w.y, h2.y, acc2);
        acc2 = fmaf(w.z, h2.z, acc2); acc2 = fmaf(w.w, h2.w, acc2);
        acc3 = fmaf(w.x, h3.x, acc3); acc3 = fmaf(w.y, h3.y, acc3);
        acc3 = fmaf(w.z, h3.z, acc3); acc3 = fmaf(w.w, h3.w, acc3);
    }
    const float bias = bg[n];
    g_gp[(size_t)(b0 + 0) * 256 + n] = acc0 + bias;
    g_gp[(size_t)(b0 + 1) * 256 + n] = acc1 + bias;
    g_gp[(size_t)(b0 + 2) * 256 + n] = acc2 + bias;
    g_gp[(size_t)(b0 + 3) * 256 + n] = acc3 + bias;
}

// ---------------------------------------------------------------------------
// Combine (R7 + 6-shfl dual reduction): 256 blocks, 1024 threads.
// smem (fp16): fp 64x256 + tp 64x256 + gpp 5x256 = 68096 B, where
// gpp[p][d] = gp[b][d] + promo[p][d]. 2 v per warp iteration.
// ---------------------------------------------------------------------------
__global__ void __launch_bounds__(1024) combine_kernel(
    const float* __restrict__ promo_tab, const float* __restrict__ Ws,
    const float* __restrict__ bs,
    const int* __restrict__ from_sqs, const int* __restrict__ to_sqs,
    const int* __restrict__ promo_types,
    float* __restrict__ out)
{
    extern __shared__ __half hsm2[];
    __half* fp_s  = hsm2;            // 16384 halves
    __half* tp_s  = hsm2 + 16384;    // 16384 halves
    __half* gpp_s = hsm2 + 32768;    // 1280 halves

    const int tid = threadIdx.x;
    const int b   = blockIdx.x;

    {
        const uint4* sf = (const uint4*)(g_fph + (size_t)b * 16384);
        const uint4* st = (const uint4*)(g_tph + (size_t)b * 16384);
        uint4* df = (uint4*)fp_s;
        uint4* dt = (uint4*)tp_s;
        df[tid] = sf[tid]; df[tid + 1024] = sf[tid + 1024];
        dt[tid] = st[tid]; dt[tid + 1024] = st[tid + 1024];
        if (tid < 640) {
            const int p  = tid >> 7;
            const int d2 = tid & 127;
            const float2 pv = ((const float2*)(promo_tab + p * 256))[d2];
            const float2 gv = ((const float2*)(g_gp + (size_t)b * 256))[d2];
            ((__half2*)gpp_s)[tid] = __floats2half2_rn(pv.x + gv.x, pv.y + gv.y);
        }
    }

    const int lane = tid & 31;
    const int warp = tid >> 5;

    const float4 wsa = *(const float4*)(Ws + lane * 8);
    const float4 wsb = *(const float4*)(Ws + lane * 8 + 4);
    const float wsr[8] = { wsa.x, wsa.y, wsa.z, wsa.w, wsb.x, wsb.y, wsb.z, wsb.w };
    const float bs0 = __ldg(bs);
    const __half2 hzero = __float2half2_rn(0.f);

    __syncthreads();

    for (int v0 = warp * 2; v0 < 1858; v0 += 64) {
        const int v1 = v0 + 1;
        const int f0 = __ldg(from_sqs + v0),    f1 = __ldg(from_sqs + v1);
        const int t0 = __ldg(to_sqs + v0),      t1 = __ldg(to_sqs + v1);
        const int p0 = __ldg(promo_types + v0), p1 = __ldg(promo_types + v1);

        const uint4 fh0 = *(const uint4*)(fp_s  + f0 * 256 + lane * 8);
        const uint4 th0 = *(const uint4*)(tp_s  + t0 * 256 + lane * 8);
        const uint4 gh0 = *(const uint4*)(gpp_s + p0 * 256 + lane * 8);
        const uint4 fh1 = *(const uint4*)(fp_s  + f1 * 256 + lane * 8);
        const uint4 th1 = *(const uint4*)(tp_s  + t1 * 256 + lane * 8);
        const uint4 gh1 = *(const uint4*)(gpp_s + p1 * 256 + lane * 8);

        const uint32_t* fw0 = (const uint32_t*)&fh0;
        const uint32_t* tw0 = (const uint32_t*)&th0;
        const uint32_t* gw0 = (const uint32_t*)&gh0;
        const uint32_t* fw1 = (const uint32_t*)&fh1;
        const uint32_t* tw1 = (const uint32_t*)&th1;
        const uint32_t* gw1 = (const uint32_t*)&gh1;

        float acc0 = 0.f, acc1 = 0.f;
        #pragma unroll
        for (int j = 0; j < 4; j++) {
            __half2 c0 = __hfma2(*(const __half2*)&fw0[j], *(const __half2*)&tw0[j],
                                 *(const __half2*)&gw0[j]);
            __half2 c1 = __hfma2(*(const __half2*)&fw1[j], *(const __half2*)&tw1[j],
                                 *(const __half2*)&gw1[j]);
            c0 = __hmax2(c0, hzero);
            c1 = __hmax2(c1, hzero);
            const float2 r0 = __half22float2(c0);
            const float2 r1 = __half22float2(c1);
            acc0 = fmaf(r0.x, wsr[2*j],     acc0);
            acc0 = fmaf(r0.y, wsr[2*j + 1], acc0);
            acc1 = fmaf(r1.x, wsr[2*j],     acc1);
            acc1 = fmaf(r1.y, wsr[2*j + 1], acc1);
        }

        // dual reduction: fold lane^16 for each chain, select halves, 4 levels
        const float a = acc0 + __shfl_xor_sync(0xffffffffu, acc0, 16);
        const float c = acc1 + __shfl_xor_sync(0xffffffffu, acc1, 16);
        float r = (lane & 16) ? c : a;
        r += __shfl_xor_sync(0xffffffffu, r, 8);
        r += __shfl_xor_sync(0xffffffffu, r, 4);
        r += __shfl_xor_sync(0xffffffffu, r, 2);
        r += __shfl_xor_sync(0xffffffffu, r, 1);
        if (lane == 0)  out[(size_t)b * 1858 + v0] = r + bs0;
        if (lane == 16) out[(size_t)b * 1858 + v1] = r + bs0;
    }
}

// ---------------------------------------------------------------------------
extern "C" void kernel_launch(void* const* d_in, const int* in_sizes, int n_in,
                              void* d_out, int out_size)
{
    (void)in_sizes; (void)n_in; (void)out_size;

    const float* hidden      = (const float*)d_in[0];
    const float* Wf          = (const float*)d_in[1];
    const float* bf          = (const float*)d_in[2];
    const float* Wt          = (const float*)d_in[3];
    const float* bt          = (const float*)d_in[4];
    const float* Wg          = (const float*)d_in[5];
    const float* bg          = (const float*)d_in[6];
    const float* promo_tab   = (const float*)d_in[7];
    const float* Ws          = (const float*)d_in[8];
    const float* bs          = (const float*)d_in[9];
    const int*   from_sqs    = (const int*)d_in[10];
    const int*   to_sqs      = (const int*)d_in[11];
    const int*   promo_types = (const int*)d_in[12];
    float*       out         = (float*)d_out;

    // 1) gather + fp16 convert pre-pass
    conv_kernel<<<4224, 256>>>(hidden, Wf, Wt);

    // 2) fp16 tensor-core fp/tp GEMM (128x256, 16 warps, 3-stage)
    cudaFuncSetAttribute(gemm_fpt_kernel,
                         cudaFuncAttributeMaxDynamicSharedMemorySize, GEMM_SMEM);
    gemm_fpt_kernel<<<dim3(2, 128), 512, GEMM_SMEM>>>(bf, bt);

    // 3) gp
    gp_kernel<<<64, 256>>>(hidden, Wg, bg);

    // 4) combine
    const int comb_smem = (16384 + 16384 + 1280) * 2;   // 68096 B
    cudaFuncSetAttribute(combine_kernel,
                         cudaFuncAttributeMaxDynamicSharedMemorySize, comb_smem);
    combine_kernel<<<256, 1024, comb_smem>>>(promo_tab, Ws, bs,
                                             from_sqs, to_sqs, promo_types, out);
}

// round 11
// speedup vs baseline: 1.1520x; 1.0050x over previous
#include <cuda_runtime.h>
#include <cuda_fp16.h>
#include <cstdint>

// ---------------------------------------------------------------------------
// SpatialPolicyHead: B=256, S=128 (rows 3..66 + row 0), H=1024, D=256, V=1858
//   fp = sq_hidden @ Wf^T + bf          (B*64, 256)
//   tp = sq_hidden @ Wt^T + bt          (B*64, 256)
//   gp = hidden[:,0,:] @ Wg^T + bg      (B, 256)
//   out[b,v] = sum_d relu(fp[b,f(v),d]*tp[b,t(v),d] + gp[b,d] + promo[p(v),d])*Ws[d] + bs
//
// R11: combine keeps gpp (gp+promo, fp16) in registers (2 LDS.128/v instead
// of 3); GEMM k-tile 64 (16 sync windows instead of 32), 2-stage.
// ---------------------------------------------------------------------------

// scratch (static device globals -- allocation-free)
__device__ __half g_Ah[16384 * 1024];   // gathered sq_hidden rows, fp16
__device__ __half g_Bh[512 * 1024];     // Wf (0..255) ++ Wt (256..511), fp16
__device__ __half g_fph[16384 * 256];   // fp results, fp16
__device__ __half g_tph[16384 * 256];   // tp results, fp16
__device__ float  g_gp [256 * 256];     // [B][256] fp32

// ---------------------------------------------------------------------------
// Pre-pass: gather + fp16-convert A; convert B.
// ---------------------------------------------------------------------------
__global__ void __launch_bounds__(256) conv_kernel(
    const float* __restrict__ hidden,
    const float* __restrict__ Wf, const float* __restrict__ Wt)
{
    const int tid = threadIdx.x;
    if (blockIdx.x < 4096) {
        const size_t base = (size_t)blockIdx.x * 1024;
        #pragma unroll
        for (int j = 0; j < 4; j++) {
            const size_t i = base + tid + j * 256;   // float4 index
            const int m  = (int)(i >> 8);
            const int c4 = (int)(i & 255);
            const int row = (m >> 6) * 128 + 3 + (m & 63);
            const float4 v = ((const float4*)(hidden + (size_t)row * 1024))[c4];
            ((__half2*)g_Ah)[2 * i]     = __floats2half2_rn(v.x, v.y);
            ((__half2*)g_Ah)[2 * i + 1] = __floats2half2_rn(v.z, v.w);
        }
    } else {
        const size_t base = (size_t)(blockIdx.x - 4096) * 1024;
        #pragma unroll
        for (int j = 0; j < 4; j++) {
            const size_t i = base + tid + j * 256;
            const int n  = (int)(i >> 8);
            const int c4 = (int)(i & 255);
            const float* src = (n < 256) ? (Wf + (size_t)n * 1024)
                                         : (Wt + (size_t)(n - 256) * 1024);
            const float4 v = ((const float4*)src)[c4];
            ((__half2*)g_Bh)[2 * i]     = __floats2half2_rn(v.x, v.y);
            ((__half2*)g_Bh)[2 * i + 1] = __floats2half2_rn(v.z, v.w);
        }
    }
}

// ---------------------------------------------------------------------------
// fp16 tensor-core GEMM: grid (2,128): x=0 -> fp, 1 -> tp.
// 128(m) x 256(n) x 64(k) block tile, 512 threads = 16 warps (4m x 4n),
// warp tile 32x64. mma.sync.m16n8k16 f16->f32, 2-stage cp.async pipeline.
// smem/stage: A 128x72h (18432 B) + B 256x72h (36864 B) = 55296 B.
// ---------------------------------------------------------------------------
#define KT 16                    // 1024/64 k-tiles
#define AST 72                   // halves per smem row (144 B)
#define ABUFH (128 * AST)
#define BBUFH (256 * AST)
#define GEMM_SMEM (2 * (ABUFH + BBUFH) * 2)   // 110592 B

__device__ __forceinline__ void mma_f16(float* c, const uint32_t* a, const uint32_t* b) {
    asm volatile(
        "mma.sync.aligned.m16n8k16.row.col.f32.f16.f16.f32 "
        "{%0,%1,%2,%3}, {%4,%5,%6,%7}, {%8,%9}, {%0,%1,%2,%3};"
        : "+f"(c[0]), "+f"(c[1]), "+f"(c[2]), "+f"(c[3])
        : "r"(a[0]), "r"(a[1]), "r"(a[2]), "r"(a[3]), "r"(b[0]), "r"(b[1]));
}

__global__ void __launch_bounds__(512) gemm_fpt_kernel(
    const float* __restrict__ bf, const float* __restrict__ bt)
{
    extern __shared__ __half hsm[];
    uint32_t sbase;
    asm("{ .reg .u64 t; cvta.to.shared.u64 t, %1; cvt.u32.u64 %0, t; }"
        : "=r"(sbase) : "l"(hsm));

    const int tid  = threadIdx.x;
    const int bn   = blockIdx.x;    // 0 = fp, 1 = tp
    const int bm   = blockIdx.y;
    const int warp = tid >> 5;
    const int lane = tid & 31;
    const int warp_m = warp >> 2;   // 0..3
    const int warp_n = warp & 3;    // 0..3
    const int lr = lane >> 2;       // 0..7
    const int lc = lane & 3;        // 0..3

    // A copy: 128 rows x 64 halves = 1024 x 16B chunks -> 2 chunks/thread
    // chunk id = tid + 512j -> row = id>>3, cc = id&7
    const __half* gAbase = g_Ah + (size_t)(bm * 128) * 1024;
    // B copy: 256 rows x 64 halves = 2048 chunks -> 4 chunks/thread
    const __half* gBbase = g_Bh + (size_t)bn * 256 * 1024;

    float acc[2][8][4];
    #pragma unroll
    for (int i = 0; i < 2; i++)
        #pragma unroll
        for (int j = 0; j < 8; j++)
            #pragma unroll
            for (int k = 0; k < 4; k++) acc[i][j][k] = 0.f;

    auto load_tile = [&](int t, int stg) {
        const uint32_t aB = sbase + (uint32_t)stg * (ABUFH + BBUFH) * 2;
        const uint32_t bB = aB + ABUFH * 2;
        #pragma unroll
        for (int j = 0; j < 2; j++) {
            const int id  = tid + 512 * j;
            const int row = id >> 3;
            const int cc  = id & 7;
            asm volatile("cp.async.ca.shared.global [%0], [%1], 16;" ::
                "r"(aB + (uint32_t)(row * (AST * 2) + cc * 16)),
                "l"(gAbase + (size_t)row * 1024 + t * 64 + cc * 8));
        }
        #pragma unroll
        for (int j = 0; j < 4; j++) {
            const int id  = tid + 512 * j;
            const int row = id >> 3;
            const int cc  = id & 7;
            asm volatile("cp.async.ca.shared.global [%0], [%1], 16;" ::
                "r"(bB + (uint32_t)(row * (AST * 2) + cc * 16)),
                "l"(gBbase + (size_t)row * 1024 + t * 64 + cc * 8));
        }
        asm volatile("cp.async.commit_group;" ::: "memory");
    };

    load_tile(0, 0);

    int stg = 0;
    for (int t = 0; t < KT; t++) {
        asm volatile("cp.async.wait_group 0;" ::: "memory");
        __syncthreads();

        if (t + 1 < KT)
            load_tile(t + 1, stg ^ 1);

        const __half* Ab = hsm + (size_t)stg * (ABUFH + BBUFH);
        const __half* Bb = Ab + ABUFH;
        #pragma unroll
        for (int ks = 0; ks < 4; ks++) {
            uint32_t afr[2][4], bfr[8][2];
            #pragma unroll
            for (int mt = 0; mt < 2; mt++) {
                const __half* p = Ab + (warp_m * 32 + mt * 16 + lr) * AST + ks * 16 + 2 * lc;
                afr[mt][0] = *(const uint32_t*)(p);
                afr[mt][1] = *(const uint32_t*)(p + 8 * AST);
                afr[mt][2] = *(const uint32_t*)(p + 8);
                afr[mt][3] = *(const uint32_t*)(p + 8 * AST + 8);
            }
            #pragma unroll
            for (int nt = 0; nt < 8; nt++) {
                const __half* q = Bb + (warp_n * 64 + nt * 8 + lr) * AST + ks * 16 + 2 * lc;
                bfr[nt][0] = *(const uint32_t*)(q);
                bfr[nt][1] = *(const uint32_t*)(q + 8);
            }
            #pragma unroll
            for (int mt = 0; mt < 2; mt++)
                #pragma unroll
                for (int nt = 0; nt < 8; nt++)
                    mma_f16(acc[mt][nt], afr[mt], bfr[nt]);
        }
        stg ^= 1;
    }

    // epilogue: bias add in fp32, store fp16 half2
    const float* bia_base = bn ? bt : bf;
    __half* outp = bn ? g_tph : g_fph;
    #pragma unroll
    for (int mt = 0; mt < 2; mt++) {
        const int gm0 = bm * 128 + warp_m * 32 + mt * 16 + lr;
        #pragma unroll
        for (int nt = 0; nt < 8; nt++) {
            const int n_loc = warp_n * 64 + nt * 8 + (lc << 1);   // 0..255
            const float b0 = bia_base[n_loc], b1 = bia_base[n_loc + 1];
            *(__half2*)&outp[(size_t)gm0 * 256 + n_loc] =
                __floats2half2_rn(acc[mt][nt][0] + b0, acc[mt][nt][1] + b1);
            *(__half2*)&outp[(size_t)(gm0 + 8) * 256 + n_loc] =
                __floats2half2_rn(acc[mt][nt][2] + b0, acc[mt][nt][3] + b1);
        }
    }
}

// ---------------------------------------------------------------------------
// gp GEMM (fp32, tiny): 64 blocks x 4 batches.
// ---------------------------------------------------------------------------
__global__ void __launch_bounds__(256) gp_kernel(
    const float* __restrict__ hidden,
    const float* __restrict__ Wg, const float* __restrict__ bg)
{
    __shared__ float sh[4][1024];
    const int tid = threadIdx.x;
    const int b0  = blockIdx.x * 4;

    #pragma unroll
    for (int i = 0; i < 4; i++) {
        const int idx = tid + i * 256;
        const int row = idx >> 8;
        const int col = idx & 255;
        ((float4*)&sh[row][0])[col] =
            ((const float4*)(hidden + (size_t)(b0 + row) * 131072))[col];
    }
    __syncthreads();

    const int n = tid;
    const float4* w4 = (const float4*)(Wg + (size_t)n * 1024);
    float acc0 = 0.f, acc1 = 0.f, acc2 = 0.f, acc3 = 0.f;
    #pragma unroll 4
    for (int k4 = 0; k4 < 256; k4++) {
        const float4 w  = w4[k4];
        const float4 h0 = ((const float4*)&sh[0][0])[k4];
        const float4 h1 = ((const float4*)&sh[1][0])[k4];
        const float4 h2 = ((const float4*)&sh[2][0])[k4];
        const float4 h3 = ((const float4*)&sh[3][0])[k4];
        acc0 = fmaf(w.x, h0.x, acc0); acc0 = fmaf(w.y, h0.y, acc0);
        acc0 = fmaf(w.z, h0.z, acc0); acc0 = fmaf(w.w, h0.w, acc0);
        acc1 = fmaf(w.x, h1.x, acc1); acc1 = fmaf(w.y, h1.y, acc1);
        acc1 = fmaf(w.z, h1.z, acc1); acc1 = fmaf(w.w, h1.w, acc1);
        acc2 = fmaf(w.x, h2.x, acc2); acc2 = fmaf(w.y, h2.y, acc2);
        acc2 = fmaf(w.z, h2.z, acc2); acc2 = fmaf(w.w, h2.w, acc2);
        acc3 = fmaf(w.x, h3.x, acc3); acc3 = fmaf(w.y, h3.y, acc3);
        acc3 = fmaf(w.z, h3.z, acc3); acc3 = fmaf(w.w, h3.w, acc3);
    }
    const float bias = bg[n];
    g_gp[(size_t)(b0 + 0) * 256 + n] = acc0 + bias;
    g_gp[(size_t)(b0 + 1) * 256 + n] = acc1 + bias;
    g_gp[(size_t)(b0 + 2) * 256 + n] = acc2 + bias;
    g_gp[(size_t)(b0 + 3) * 256 + n] = acc3 + bias;
}

// ---------------------------------------------------------------------------
// Combine: 256 blocks (one per batch), 1024 threads (32 warps).
// smem (fp16): fp 64x256 + tp 64x256 = 65536 B.
// gpp[p][d] = gp[b][d] + promo[p][d] held in REGISTERS (5x4 half2 per lane).
// Per v per lane: 2 x LDS.128. 2 v per warp iteration; 6-shfl dual reduce.
// ---------------------------------------------------------------------------
__global__ void __launch_bounds__(1024) combine_kernel(
    const float* __restrict__ promo_tab, const float* __restrict__ Ws,
    const float* __restrict__ bs,
    const int* __restrict__ from_sqs, const int* __restrict__ to_sqs,
    const int* __restrict__ promo_types,
    float* __restrict__ out)
{
    extern __shared__ __half hsm2[];
    __half* fp_s = hsm2;            // 16384 halves
    __half* tp_s = hsm2 + 16384;    // 16384 halves

    const int tid = threadIdx.x;
    const int b   = blockIdx.x;

    {
        const uint4* sf = (const uint4*)(g_fph + (size_t)b * 16384);
        const uint4* st = (const uint4*)(g_tph + (size_t)b * 16384);
        uint4* df = (uint4*)fp_s;
        uint4* dt = (uint4*)tp_s;
        df[tid] = sf[tid]; df[tid + 1024] = sf[tid + 1024];
        dt[tid] = st[tid]; dt[tid + 1024] = st[tid + 1024];
    }

    const int lane = tid & 31;
    const int warp = tid >> 5;

    // register-resident gpp: for each promo type p, halves for d = lane*8..+7
    __half2 gpp_r[5][4];
    {
        const float* gpb = g_gp + (size_t)b * 256 + lane * 8;
        float gv[8];
        #pragma unroll
        for (int j = 0; j < 8; j++) gv[j] = gpb[j];
        #pragma unroll
        for (int p = 0; p < 5; p++) {
            const float* pr = promo_tab + p * 256 + lane * 8;
            #pragma unroll
            for (int j = 0; j < 4; j++)
                gpp_r[p][j] = __floats2half2_rn(gv[2*j] + pr[2*j],
                                                gv[2*j + 1] + pr[2*j + 1]);
        }
    }

    const float4 wsa = *(const float4*)(Ws + lane * 8);
    const float4 wsb = *(const float4*)(Ws + lane * 8 + 4);
    const float wsr[8] = { wsa.x, wsa.y, wsa.z, wsa.w, wsb.x, wsb.y, wsb.z, wsb.w };
    const float bs0 = __ldg(bs);
    const __half2 hzero = __float2half2_rn(0.f);

    __syncthreads();

    for (int v0 = warp * 2; v0 < 1858; v0 += 64) {
        const int v1 = v0 + 1;
        const int f0 = __ldg(from_sqs + v0),    f1 = __ldg(from_sqs + v1);
        const int t0 = __ldg(to_sqs + v0),      t1 = __ldg(to_sqs + v1);
        const int p0 = __ldg(promo_types + v0), p1 = __ldg(promo_types + v1);

        const uint4 fh0 = *(const uint4*)(fp_s + f0 * 256 + lane * 8);
        const uint4 th0 = *(const uint4*)(tp_s + t0 * 256 + lane * 8);
        const uint4 fh1 = *(const uint4*)(fp_s + f1 * 256 + lane * 8);
        const uint4 th1 = *(const uint4*)(tp_s + t1 * 256 + lane * 8);

        const uint32_t* fw0 = (const uint32_t*)&fh0;
        const uint32_t* tw0 = (const uint32_t*)&th0;
        const uint32_t* fw1 = (const uint32_t*)&fh1;
        const uint32_t* tw1 = (const uint32_t*)&th1;

        float acc0 = 0.f, acc1 = 0.f;
        #pragma unroll
        for (int j = 0; j < 4; j++) {
            __half2 c0 = __hfma2(*(const __half2*)&fw0[j], *(const __half2*)&tw0[j],
                                 gpp_r[p0][j]);
            __half2 c1 = __hfma2(*(const __half2*)&fw1[j], *(const __half2*)&tw1[j],
                                 gpp_r[p1][j]);
            c0 = __hmax2(c0, hzero);
            c1 = __hmax2(c1, hzero);
            const float2 r0 = __half22float2(c0);
            const float2 r1 = __half22float2(c1);
            acc0 = fmaf(r0.x, wsr[2*j],     acc0);
            acc0 = fmaf(r0.y, wsr[2*j + 1], acc0);
            acc1 = fmaf(r1.x, wsr[2*j],     acc1);
            acc1 = fmaf(r1.y, wsr[2*j + 1], acc1);
        }

        // dual reduction: fold lane^16 for each chain, select halves, 4 levels
        const float a = acc0 + __shfl_xor_sync(0xffffffffu, acc0, 16);
        const float c = acc1 + __shfl_xor_sync(0xffffffffu, acc1, 16);
        float r = (lane & 16) ? c : a;
        r += __shfl_xor_sync(0xffffffffu, r, 8);
        r += __shfl_xor_sync(0xffffffffu, r, 4);
        r += __shfl_xor_sync(0xffffffffu, r, 2);
        r += __shfl_xor_sync(0xffffffffu, r, 1);
        if (lane == 0)  out[(size_t)b * 1858 + v0] = r + bs0;
        if (lane == 16) out[(size_t)b * 1858 + v1] = r + bs0;
    }
}

// ---------------------------------------------------------------------------
extern "C" void kernel_launch(void* const* d_in, const int* in_sizes, int n_in,
                              void* d_out, int out_size)
{
    (void)in_sizes; (void)n_in; (void)out_size;

    const float* hidden      = (const float*)d_in[0];
    const float* Wf          = (const float*)d_in[1];
    const float* bf          = (const float*)d_in[2];
    const float* Wt          = (const float*)d_in[3];
    const float* bt          = (const float*)d_in[4];
    const float* Wg          = (const float*)d_in[5];
    const float* bg          = (const float*)d_in[6];
    const float* promo_tab   = (const float*)d_in[7];
    const float* Ws          = (const float*)d_in[8];
    const float* bs          = (const float*)d_in[9];
    const int*   from_sqs    = (const int*)d_in[10];
    const int*   to_sqs      = (const int*)d_in[11];
    const int*   promo_types = (const int*)d_in[12];
    float*       out         = (float*)d_out;

    // 1) gather + fp16 convert pre-pass
    conv_kernel<<<4224, 256>>>(hidden, Wf, Wt);

    // 2) fp16 tensor-core fp/tp GEMM (128x256x64, 16 warps, 2-stage)
    cudaFuncSetAttribute(gemm_fpt_kernel,
                         cudaFuncAttributeMaxDynamicSharedMemorySize, GEMM_SMEM);
    gemm_fpt_kernel<<<dim3(2, 128), 512, GEMM_SMEM>>>(bf, bt);

    // 3) gp
    gp_kernel<<<64, 256>>>(hidden, Wg, bg);

    // 4) combine (gpp in registers, smem = fp/tp only)
    const int comb_smem = (16384 + 16384) * 2;   // 65536 B
    cudaFuncSetAttribute(combine_kernel,
                         cudaFuncAttributeMaxDynamicSharedMemorySize, comb_smem);
    combine_kernel<<<256, 1024, comb_smem>>>(promo_tab, Ws, bs,
                                             from_sqs, to_sqs, promo_types, out);
}

// round 12
// speedup vs baseline: 1.2505x; 1.0856x over previous
#include <cuda_runtime.h>
#include <cuda_fp16.h>
#include <cstdint>

// ---------------------------------------------------------------------------
// SpatialPolicyHead: B=256, S=128 (rows 3..66 + row 0), H=1024, D=256, V=1858
//   fp = sq_hidden @ Wf^T + bf          (B*64, 256)
//   tp = sq_hidden @ Wt^T + bt          (B*64, 256)
//   gp = hidden[:,0,:] @ Wg^T + bg      (B, 256)
//   out[b,v] = sum_d relu(fp[b,f(v),d]*tp[b,t(v),d] + gp[b,d] + promo[p(v),d])*Ws[d] + bs
//
// R12: best-of assembly -- R11 GEMM (k64, 16 warps, 2-stage, -13us measured)
// + R10 combine (smem gpp, 54us measured). conv/gp unchanged.
// ---------------------------------------------------------------------------

// scratch (static device globals -- allocation-free)
__device__ __half g_Ah[16384 * 1024];   // gathered sq_hidden rows, fp16
__device__ __half g_Bh[512 * 1024];     // Wf (0..255) ++ Wt (256..511), fp16
__device__ __half g_fph[16384 * 256];   // fp results, fp16
__device__ __half g_tph[16384 * 256];   // tp results, fp16
__device__ float  g_gp [256 * 256];     // [B][256] fp32

// ---------------------------------------------------------------------------
// Pre-pass: gather + fp16-convert A; convert B.
// ---------------------------------------------------------------------------
__global__ void __launch_bounds__(256) conv_kernel(
    const float* __restrict__ hidden,
    const float* __restrict__ Wf, const float* __restrict__ Wt)
{
    const int tid = threadIdx.x;
    if (blockIdx.x < 4096) {
        const size_t base = (size_t)blockIdx.x * 1024;
        #pragma unroll
        for (int j = 0; j < 4; j++) {
            const size_t i = base + tid + j * 256;   // float4 index
            const int m  = (int)(i >> 8);
            const int c4 = (int)(i & 255);
            const int row = (m >> 6) * 128 + 3 + (m & 63);
            const float4 v = ((const float4*)(hidden + (size_t)row * 1024))[c4];
            ((__half2*)g_Ah)[2 * i]     = __floats2half2_rn(v.x, v.y);
            ((__half2*)g_Ah)[2 * i + 1] = __floats2half2_rn(v.z, v.w);
        }
    } else {
        const size_t base = (size_t)(blockIdx.x - 4096) * 1024;
        #pragma unroll
        for (int j = 0; j < 4; j++) {
            const size_t i = base + tid + j * 256;
            const int n  = (int)(i >> 8);
            const int c4 = (int)(i & 255);
            const float* src = (n < 256) ? (Wf + (size_t)n * 1024)
                                         : (Wt + (size_t)(n - 256) * 1024);
            const float4 v = ((const float4*)src)[c4];
            ((__half2*)g_Bh)[2 * i]     = __floats2half2_rn(v.x, v.y);
            ((__half2*)g_Bh)[2 * i + 1] = __floats2half2_rn(v.z, v.w);
        }
    }
}

// ---------------------------------------------------------------------------
// fp16 tensor-core GEMM: grid (2,128): x=0 -> fp, 1 -> tp.
// 128(m) x 256(n) x 64(k) block tile, 512 threads = 16 warps (4m x 4n),
// warp tile 32x64. mma.sync.m16n8k16 f16->f32, 2-stage cp.async pipeline.
// smem/stage: A 128x72h (18432 B) + B 256x72h (36864 B) = 55296 B.
// ---------------------------------------------------------------------------
#define KT 16                    // 1024/64 k-tiles
#define AST 72                   // halves per smem row (144 B)
#define ABUFH (128 * AST)
#define BBUFH (256 * AST)
#define GEMM_SMEM (2 * (ABUFH + BBUFH) * 2)   // 110592 B

__device__ __forceinline__ void mma_f16(float* c, const uint32_t* a, const uint32_t* b) {
    asm volatile(
        "mma.sync.aligned.m16n8k16.row.col.f32.f16.f16.f32 "
        "{%0,%1,%2,%3}, {%4,%5,%6,%7}, {%8,%9}, {%0,%1,%2,%3};"
        : "+f"(c[0]), "+f"(c[1]), "+f"(c[2]), "+f"(c[3])
        : "r"(a[0]), "r"(a[1]), "r"(a[2]), "r"(a[3]), "r"(b[0]), "r"(b[1]));
}

__global__ void __launch_bounds__(512) gemm_fpt_kernel(
    const float* __restrict__ bf, const float* __restrict__ bt)
{
    extern __shared__ __half hsm[];
    uint32_t sbase;
    asm("{ .reg .u64 t; cvta.to.shared.u64 t, %1; cvt.u32.u64 %0, t; }"
        : "=r"(sbase) : "l"(hsm));

    const int tid  = threadIdx.x;
    const int bn   = blockIdx.x;    // 0 = fp, 1 = tp
    const int bm   = blockIdx.y;
    const int warp = tid >> 5;
    const int lane = tid & 31;
    const int warp_m = warp >> 2;   // 0..3
    const int warp_n = warp & 3;    // 0..3
    const int lr = lane >> 2;       // 0..7
    const int lc = lane & 3;        // 0..3

    const __half* gAbase = g_Ah + (size_t)(bm * 128) * 1024;
    const __half* gBbase = g_Bh + (size_t)bn * 256 * 1024;

    float acc[2][8][4];
    #pragma unroll
    for (int i = 0; i < 2; i++)
        #pragma unroll
        for (int j = 0; j < 8; j++)
            #pragma unroll
            for (int k = 0; k < 4; k++) acc[i][j][k] = 0.f;

    auto load_tile = [&](int t, int stg) {
        const uint32_t aB = sbase + (uint32_t)stg * (ABUFH + BBUFH) * 2;
        const uint32_t bB = aB + ABUFH * 2;
        #pragma unroll
        for (int j = 0; j < 2; j++) {
            const int id  = tid + 512 * j;
            const int row = id >> 3;
            const int cc  = id & 7;
            asm volatile("cp.async.ca.shared.global [%0], [%1], 16;" ::
                "r"(aB + (uint32_t)(row * (AST * 2) + cc * 16)),
                "l"(gAbase + (size_t)row * 1024 + t * 64 + cc * 8));
        }
        #pragma unroll
        for (int j = 0; j < 4; j++) {
            const int id  = tid + 512 * j;
            const int row = id >> 3;
            const int cc  = id & 7;
            asm volatile("cp.async.ca.shared.global [%0], [%1], 16;" ::
                "r"(bB + (uint32_t)(row * (AST * 2) + cc * 16)),
                "l"(gBbase + (size_t)row * 1024 + t * 64 + cc * 8));
        }
        asm volatile("cp.async.commit_group;" ::: "memory");
    };

    load_tile(0, 0);

    int stg = 0;
    for (int t = 0; t < KT; t++) {
        asm volatile("cp.async.wait_group 0;" ::: "memory");
        __syncthreads();

        if (t + 1 < KT)
            load_tile(t + 1, stg ^ 1);

        const __half* Ab = hsm + (size_t)stg * (ABUFH + BBUFH);
        const __half* Bb = Ab + ABUFH;
        #pragma unroll
        for (int ks = 0; ks < 4; ks++) {
            uint32_t afr[2][4], bfr[8][2];
            #pragma unroll
            for (int mt = 0; mt < 2; mt++) {
                const __half* p = Ab + (warp_m * 32 + mt * 16 + lr) * AST + ks * 16 + 2 * lc;
                afr[mt][0] = *(const uint32_t*)(p);
                afr[mt][1] = *(const uint32_t*)(p + 8 * AST);
                afr[mt][2] = *(const uint32_t*)(p + 8);
                afr[mt][3] = *(const uint32_t*)(p + 8 * AST + 8);
            }
            #pragma unroll
            for (int nt = 0; nt < 8; nt++) {
                const __half* q = Bb + (warp_n * 64 + nt * 8 + lr) * AST + ks * 16 + 2 * lc;
                bfr[nt][0] = *(const uint32_t*)(q);
                bfr[nt][1] = *(const uint32_t*)(q + 8);
            }
            #pragma unroll
            for (int mt = 0; mt < 2; mt++)
                #pragma unroll
                for (int nt = 0; nt < 8; nt++)
                    mma_f16(acc[mt][nt], afr[mt], bfr[nt]);
        }
        stg ^= 1;
    }

    // epilogue: bias add in fp32, store fp16 half2
    const float* bia_base = bn ? bt : bf;
    __half* outp = bn ? g_tph : g_fph;
    #pragma unroll
    for (int mt = 0; mt < 2; mt++) {
        const int gm0 = bm * 128 + warp_m * 32 + mt * 16 + lr;
        #pragma unroll
        for (int nt = 0; nt < 8; nt++) {
            const int n_loc = warp_n * 64 + nt * 8 + (lc << 1);   // 0..255
            const float b0 = bia_base[n_loc], b1 = bia_base[n_loc + 1];
            *(__half2*)&outp[(size_t)gm0 * 256 + n_loc] =
                __floats2half2_rn(acc[mt][nt][0] + b0, acc[mt][nt][1] + b1);
            *(__half2*)&outp[(size_t)(gm0 + 8) * 256 + n_loc] =
                __floats2half2_rn(acc[mt][nt][2] + b0, acc[mt][nt][3] + b1);
        }
    }
}

// ---------------------------------------------------------------------------
// gp GEMM (fp32, tiny): 64 blocks x 4 batches.
// ---------------------------------------------------------------------------
__global__ void __launch_bounds__(256) gp_kernel(
    const float* __restrict__ hidden,
    const float* __restrict__ Wg, const float* __restrict__ bg)
{
    __shared__ float sh[4][1024];
    const int tid = threadIdx.x;
    const int b0  = blockIdx.x * 4;

    #pragma unroll
    for (int i = 0; i < 4; i++) {
        const int idx = tid + i * 256;
        const int row = idx >> 8;
        const int col = idx & 255;
        ((float4*)&sh[row][0])[col] =
            ((const float4*)(hidden + (size_t)(b0 + row) * 131072))[col];
    }
    __syncthreads();

    const int n = tid;
    const float4* w4 = (const float4*)(Wg + (size_t)n * 1024);
    float acc0 = 0.f, acc1 = 0.f, acc2 = 0.f, acc3 = 0.f;
    #pragma unroll 4
    for (int k4 = 0; k4 < 256; k4++) {
        const float4 w  = w4[k4];
        const float4 h0 = ((const float4*)&sh[0][0])[k4];
        const float4 h1 = ((const float4*)&sh[1][0])[k4];
        const float4 h2 = ((const float4*)&sh[2][0])[k4];
        const float4 h3 = ((const float4*)&sh[3][0])[k4];
        acc0 = fmaf(w.x, h0.x, acc0); acc0 = fmaf(w.y, h0.y, acc0);
        acc0 = fmaf(w.z, h0.z, acc0); acc0 = fmaf(w.w, h0.w, acc0);
        acc1 = fmaf(w.x, h1.x, acc1); acc1 = fmaf(w.y, h1.y, acc1);
        acc1 = fmaf(w.z, h1.z, acc1); acc1 = fmaf(w.w, h1.w, acc1);
        acc2 = fmaf(w.x, h2.x, acc2); acc2 = fmaf(w.y, h2.y, acc2);
        acc2 = fmaf(w.z, h2.z, acc2); acc2 = fmaf(w.w, h2.w, acc2);
        acc3 = fmaf(w.x, h3.x, acc3); acc3 = fmaf(w.y, h3.y, acc3);
        acc3 = fmaf(w.z, h3.z, acc3); acc3 = fmaf(w.w, h3.w, acc3);
    }
    const float bias = bg[n];
    g_gp[(size_t)(b0 + 0) * 256 + n] = acc0 + bias;
    g_gp[(size_t)(b0 + 1) * 256 + n] = acc1 + bias;
    g_gp[(size_t)(b0 + 2) * 256 + n] = acc2 + bias;
    g_gp[(size_t)(b0 + 3) * 256 + n] = acc3 + bias;
}

// ---------------------------------------------------------------------------
// Combine (R10 proven config): 256 blocks, 1024 threads.
// smem (fp16): fp 64x256 + tp 64x256 + gpp 5x256 = 68096 B, where
// gpp[p][d] = gp[b][d] + promo[p][d]. 2 v per warp iter; 6-shfl dual reduce.
// ---------------------------------------------------------------------------
__global__ void __launch_bounds__(1024) combine_kernel(
    const float* __restrict__ promo_tab, const float* __restrict__ Ws,
    const float* __restrict__ bs,
    const int* __restrict__ from_sqs, const int* __restrict__ to_sqs,
    const int* __restrict__ promo_types,
    float* __restrict__ out)
{
    extern __shared__ __half hsm2[];
    __half* fp_s  = hsm2;            // 16384 halves
    __half* tp_s  = hsm2 + 16384;    // 16384 halves
    __half* gpp_s = hsm2 + 32768;    // 1280 halves

    const int tid = threadIdx.x;
    const int b   = blockIdx.x;

    {
        const uint4* sf = (const uint4*)(g_fph + (size_t)b * 16384);
        const uint4* st = (const uint4*)(g_tph + (size_t)b * 16384);
        uint4* df = (uint4*)fp_s;
        uint4* dt = (uint4*)tp_s;
        df[tid] = sf[tid]; df[tid + 1024] = sf[tid + 1024];
        dt[tid] = st[tid]; dt[tid + 1024] = st[tid + 1024];
        if (tid < 640) {
            const int p  = tid >> 7;
            const int d2 = tid & 127;
            const float2 pv = ((const float2*)(promo_tab + p * 256))[d2];
            const float2 gv = ((const float2*)(g_gp + (size_t)b * 256))[d2];
            ((__half2*)gpp_s)[tid] = __floats2half2_rn(pv.x + gv.x, pv.y + gv.y);
        }
    }

    const int lane = tid & 31;
    const int warp = tid >> 5;

    const float4 wsa = *(const float4*)(Ws + lane * 8);
    const float4 wsb = *(const float4*)(Ws + lane * 8 + 4);
    const float wsr[8] = { wsa.x, wsa.y, wsa.z, wsa.w, wsb.x, wsb.y, wsb.z, wsb.w };
    const float bs0 = __ldg(bs);
    const __half2 hzero = __float2half2_rn(0.f);

    __syncthreads();

    for (int v0 = warp * 2; v0 < 1858; v0 += 64) {
        const int v1 = v0 + 1;
        const int f0 = __ldg(from_sqs + v0),    f1 = __ldg(from_sqs + v1);
        const int t0 = __ldg(to_sqs + v0),      t1 = __ldg(to_sqs + v1);
        const int p0 = __ldg(promo_types + v0), p1 = __ldg(promo_types + v1);

        const uint4 fh0 = *(const uint4*)(fp_s  + f0 * 256 + lane * 8);
        const uint4 th0 = *(const uint4*)(tp_s  + t0 * 256 + lane * 8);
        const uint4 gh0 = *(const uint4*)(gpp_s + p0 * 256 + lane * 8);
        const uint4 fh1 = *(const uint4*)(fp_s  + f1 * 256 + lane * 8);
        const uint4 th1 = *(const uint4*)(tp_s  + t1 * 256 + lane * 8);
        const uint4 gh1 = *(const uint4*)(gpp_s + p1 * 256 + lane * 8);

        const uint32_t* fw0 = (const uint32_t*)&fh0;
        const uint32_t* tw0 = (const uint32_t*)&th0;
        const uint32_t* gw0 = (const uint32_t*)&gh0;
        const uint32_t* fw1 = (const uint32_t*)&fh1;
        const uint32_t* tw1 = (const uint32_t*)&th1;
        const uint32_t* gw1 = (const uint32_t*)&gh1;

        float acc0 = 0.f, acc1 = 0.f;
        #pragma unroll
        for (int j = 0; j < 4; j++) {
            __half2 c0 = __hfma2(*(const __half2*)&fw0[j], *(const __half2*)&tw0[j],
                                 *(const __half2*)&gw0[j]);
            __half2 c1 = __hfma2(*(const __half2*)&fw1[j], *(const __half2*)&tw1[j],
                                 *(const __half2*)&gw1[j]);
            c0 = __hmax2(c0, hzero);
            c1 = __hmax2(c1, hzero);
            const float2 r0 = __half22float2(c0);
            const float2 r1 = __half22float2(c1);
            acc0 = fmaf(r0.x, wsr[2*j],     acc0);
            acc0 = fmaf(r0.y, wsr[2*j + 1], acc0);
            acc1 = fmaf(r1.x, wsr[2*j],     acc1);
            acc1 = fmaf(r1.y, wsr[2*j + 1], acc1);
        }

        // dual reduction: fold lane^16 for each chain, select halves, 4 levels
        const float a = acc0 + __shfl_xor_sync(0xffffffffu, acc0, 16);
        const float c = acc1 + __shfl_xor_sync(0xffffffffu, acc1, 16);
        float r = (lane & 16) ? c : a;
        r += __shfl_xor_sync(0xffffffffu, r, 8);
        r += __shfl_xor_sync(0xffffffffu, r, 4);
        r += __shfl_xor_sync(0xffffffffu, r, 2);
        r += __shfl_xor_sync(0xffffffffu, r, 1);
        if (lane == 0)  out[(size_t)b * 1858 + v0] = r + bs0;
        if (lane == 16) out[(size_t)b * 1858 + v1] = r + bs0;
    }
}

// ---------------------------------------------------------------------------
extern "C" void kernel_launch(void* const* d_in, const int* in_sizes, int n_in,
                              void* d_out, int out_size)
{
    (void)in_sizes; (void)n_in; (void)out_size;

    const float* hidden      = (const float*)d_in[0];
    const float* Wf          = (const float*)d_in[1];
    const float* bf          = (const float*)d_in[2];
    const float* Wt          = (const float*)d_in[3];
    const float* bt          = (const float*)d_in[4];
    const float* Wg          = (const float*)d_in[5];
    const float* bg          = (const float*)d_in[6];
    const float* promo_tab   = (const float*)d_in[7];
    const float* Ws          = (const float*)d_in[8];
    const float* bs          = (const float*)d_in[9];
    const int*   from_sqs    = (const int*)d_in[10];
    const int*   to_sqs      = (const int*)d_in[11];
    const int*   promo_types = (const int*)d_in[12];
    float*       out         = (float*)d_out;

    // 1) gather + fp16 convert pre-pass
    conv_kernel<<<4224, 256>>>(hidden, Wf, Wt);

    // 2) fp16 tensor-core fp/tp GEMM (128x256x64, 16 warps, 2-stage)
    cudaFuncSetAttribute(gemm_fpt_kernel,
                         cudaFuncAttributeMaxDynamicSharedMemorySize, GEMM_SMEM);
    gemm_fpt_kernel<<<dim3(2, 128), 512, GEMM_SMEM>>>(bf, bt);

    // 3) gp
    gp_kernel<<<64, 256>>>(hidden, Wg, bg);

    // 4) combine (R10 proven config)
    const int comb_smem = (16384 + 16384 + 1280) * 2;   // 68096 B
    cudaFuncSetAttribute(combine_kernel,
                         cudaFuncAttributeMaxDynamicSharedMemorySize, comb_smem);
    combine_kernel<<<256, 1024, comb_smem>>>(promo_tab, Ws, bs,
                                             from_sqs, to_sqs, promo_types, out);
}